// round 13
// baseline (speedup 1.0000x reference)
#include <cuda_runtime.h>
#include <cstdint>

#define BATCH 16
#define CH    64
#define HH    256
#define WW    256
#define M2    20
#define NRR   40
#define NIMG  (BATCH*CH)     /* 1024  */
#define NROW  (NIMG*HH)      /* 262144 */

// ---------------- scratch (device globals; no allocation allowed) ----------
__device__ float2 g_tw[256];          // e^{+2*pi*i*t/256}
__device__ float  g_Bhi[256*40];      // fwdW basis hi (tf32-exact values)
__device__ float  g_Blo[256*40];      // fwdW basis lo
__device__ float2 g_Y[NROW*M2];       // forward-W result  [img*256+h][k2]
__device__ float2 g_X[NIMG*NRR*M2];   // forward modes     [img][r][k2]
__device__ float2 g_O[NIMG*NRR*M2];   // mixed modes
__device__ float2 g_W[800*4096];      // transposed weights [mode][i*64+o]

__device__ __forceinline__ float tf32r(float v) {
    uint32_t u;
    asm("cvt.rna.tf32.f32 %0, %1;" : "=r"(u) : "f"(v));
    return __uint_as_float(u);
}

#define MMA_TF32(d, a0,a1,a2,a3, b0,b1) \
  asm volatile("mma.sync.aligned.m16n8k8.row.col.f32.tf32.tf32.f32 " \
      "{%0,%1,%2,%3}, {%4,%5,%6,%7}, {%8,%9}, {%0,%1,%2,%3};" \
      : "+f"(d[0]), "+f"(d[1]), "+f"(d[2]), "+f"(d[3]) \
      : "r"(a0), "r"(a1), "r"(a2), "r"(a3), "r"(b0), "r"(b1))

// ---------------- launch 1: twiddles + tf32 split basis --------------------
__global__ void initT() {
    int t = threadIdx.x;   // t = w (0..255)
    const double TWO_PI = 6.283185307179586476925286766559;
    double a = TWO_PI * (double)t / 256.0;
    g_tw[t] = make_float2((float)cos(a), (float)sin(a));
    for (int j = 0; j < 20; ++j) {
        double ph = TWO_PI * (double)(t * j) / 256.0;
        double cv = cos(ph), sv = -sin(ph);
        float ch = tf32r((float)cv);
        float cl = tf32r((float)(cv - (double)ch));
        float sh = tf32r((float)sv);
        float sl = tf32r((float)(sv - (double)sh));
        g_Bhi[t*40 + 2*j]     = ch;  g_Blo[t*40 + 2*j]     = cl;
        g_Bhi[t*40 + 2*j + 1] = sh;  g_Blo[t*40 + 2*j + 1] = sl;
    }
}

// ---------------- launches 2,3: weight transpose ----------------------------
__global__ __launch_bounds__(1024) void wtrans(const float* __restrict__ wr, const float* __restrict__ wi,
                                               int base) {
    __shared__ float2 tile[32][33];
    int tx = threadIdx.x, ty = threadIdx.y;
    int u0 = blockIdx.x * 32, o0 = blockIdx.y * 32;
    int off = o0 + tx;
    int u = u0 + ty;
    if (off < 400) tile[ty][tx] = make_float2(wr[u*400 + off], wi[u*400 + off]);
    __syncthreads();
    int offw = o0 + ty;
    if (offw < 400) g_W[(size_t)(base + offw)*4096 + u0 + tx] = tile[tx][ty];
}

// ---------------- stage 1: partial rfft along W via tensor cores -----------
// Y[262144 x 40] = tf32(x)[262144 x 256] * (Bhi + Blo)[256 x 40]
// Per CTA: 128 rows; 8 warps x 16 rows; K chunked by 32.
#define SMEM_FWDW (25088*4)
__global__ __launch_bounds__(256) void fwdWmma(const float* __restrict__ x) {
    extern __shared__ float sm[];
    float* As = sm;            // [128][36] padded (18KB)
    float* Bs = sm + 4608;     // Bhi [256][40] then Blo [256][40] (80KB)
    int t = threadIdx.x;
    int lane = t & 31, wid = t >> 5;
    int g = lane >> 2, tig = lane & 3;
    // fill basis SMEM
    for (int i = t; i < 2560; i += 256) ((float4*)Bs)[i] = ((const float4*)g_Bhi)[i];
    for (int i = t; i < 2560; i += 256) ((float4*)(Bs + 10240))[i] = ((const float4*)g_Blo)[i];
    float acc[5][4];
    #pragma unroll
    for (int n = 0; n < 5; ++n)
        #pragma unroll
        for (int q = 0; q < 4; ++q) acc[n][q] = 0.f;
    const float4* xg = (const float4*)x + ((size_t)blockIdx.x * 128) * 64;
    for (int kc = 0; kc < 8; ++kc) {
        __syncthreads();
        #pragma unroll
        for (int n = 0; n < 4; ++n) {
            int idx = t + n*256;
            int row = idx >> 3, gg = idx & 7;
            float4 v = xg[(size_t)row*64 + kc*8 + gg];
            float4 w = make_float4(tf32r(v.x), tf32r(v.y), tf32r(v.z), tf32r(v.w));
            *(float4*)(As + row*36 + gg*4) = w;
        }
        __syncthreads();
        #pragma unroll
        for (int ks = 0; ks < 4; ++ks) {
            const float* ab = As + (wid*16 + g)*36 + ks*8 + tig;
            uint32_t a0 = __float_as_uint(ab[0]);
            uint32_t a1 = __float_as_uint(ab[8*36]);
            uint32_t a2 = __float_as_uint(ab[4]);
            uint32_t a3 = __float_as_uint(ab[8*36 + 4]);
            const float* bb = Bs + (kc*32 + ks*8 + tig)*40 + g;
            #pragma unroll
            for (int nt = 0; nt < 5; ++nt) {
                uint32_t bh0 = __float_as_uint(bb[nt*8]);
                uint32_t bh1 = __float_as_uint(bb[4*40 + nt*8]);
                MMA_TF32(acc[nt], a0, a1, a2, a3, bh0, bh1);
                uint32_t bl0 = __float_as_uint(bb[10240 + nt*8]);
                uint32_t bl1 = __float_as_uint(bb[10240 + 4*40 + nt*8]);
                MMA_TF32(acc[nt], a0, a1, a2, a3, bl0, bl1);
            }
        }
    }
    float* Yf = (float*)g_Y;
    size_t row0 = (size_t)blockIdx.x*128 + wid*16 + g;
    #pragma unroll
    for (int nt = 0; nt < 5; ++nt) {
        int n0 = nt*8 + 2*tig;
        *(float2*)(Yf + row0*40 + n0)       = make_float2(acc[nt][0], acc[nt][1]);
        *(float2*)(Yf + (row0 + 8)*40 + n0) = make_float2(acc[nt][2], acc[nt][3]);
    }
}

// ---------------- stage 2: partial complex DFT along H (radix-4 h-fold) ----
__global__ __launch_bounds__(256) void fwdH() {
    __shared__ float2 Ys[4*1288];   // 4 classes, padded stride 1288 (bank offset 8)
    int t = threadIdx.x, img = blockIdx.x;
    const float2* src = &g_Y[(size_t)img * 5120];
    for (int i = t; i < 5120; i += 256) {
        int m = i / 1280, rsd = i - m*1280;
        Ys[m*1288 + rsd] = src[i];
    }
    __syncthreads();
    for (int i = t; i < 1280; i += 256) {
        float2 a0 = Ys[i], a1 = Ys[1288 + i], a2 = Ys[2576 + i], a3 = Ys[3864 + i];
        float Ax = a0.x - a2.x, Ay = a0.y - a2.y;
        float Bx = a1.x - a3.x, By = a1.y - a3.y;
        float Sx = a0.x + a2.x, Sy = a0.y + a2.y;
        float Tx = a1.x + a3.x, Ty = a1.y + a3.y;
        Ys[i]        = make_float2(Sx + Tx, Sy + Ty);   // q=0
        Ys[1288 + i] = make_float2(Ax + By, Ay - Bx);   // q=1: A - iB
        Ys[2576 + i] = make_float2(Sx - Tx, Sy - Ty);   // q=2
        Ys[3864 + i] = make_float2(Ax - By, Ay + Bx);   // q=3: A + iB
    }
    __syncthreads();
    if (t >= 200) return;
    int r = t / 5, j0 = t - 5*(t/5);          // r 0..39, j0 0..4
    int k1 = r + (r >= 20 ? 216 : 0);
    const float2* base = Ys + (r & 3)*1288 + j0;
    float2 tw = g_tw[k1];
    float c1 = tw.x, s1 = -tw.y;              // step e^{-i th}
    float c = 1.f, s = 0.f;
    float Xr[4] = {0,0,0,0}, Xi[4] = {0,0,0,0};
    for (int h = 0; h < 64; ++h) {
        #pragma unroll
        for (int jj = 0; jj < 4; ++jj) {
            float2 y = base[h*20 + 5*jj];
            Xr[jj] = fmaf(y.x, c, Xr[jj]);  Xr[jj] = fmaf(-y.y, s, Xr[jj]);
            Xi[jj] = fmaf(y.y, c, Xi[jj]);  Xi[jj] = fmaf(y.x, s, Xi[jj]);
        }
        float cn = fmaf(c, c1, -(s*s1)); s = fmaf(s, c1, c*s1); c = cn;
    }
    #pragma unroll
    for (int jj = 0; jj < 4; ++jj)
        g_X[(size_t)img*800 + r*20 + j0 + 5*jj] = make_float2(Xr[jj], Xi[jj]);
}

// ---------------- stage 3: per-mode complex channel mixing (batch-split) ---
__global__ __launch_bounds__(256) void mixk() {
    __shared__ float2 Xs[512];    // [blocal*64+i], blocal 0..7
    __shared__ float2 Ws[4096];   // [i*64+o]
    int t = threadIdx.x, mo = blockIdx.x, half = blockIdx.y;
    for (int u = t; u < 512; u += 256) Xs[u] = g_X[(size_t)(half*512 + u)*800 + mo];
    const float4* wsrc = (const float4*)&g_W[(size_t)mo*4096];
    for (int u = t; u < 2048; u += 256) ((float4*)Ws)[u] = wsrc[u];
    __syncthreads();
    int o = t & 63, b0 = t >> 6;              // b0 0..3
    float ar[2] = {0,0}, ai[2] = {0,0};
    for (int i = 0; i < 64; ++i) {
        float2 Wv = Ws[i*64 + o];
        #pragma unroll
        for (int j = 0; j < 2; ++j) {
            float2 X = Xs[(b0 + 4*j)*64 + i];
            ar[j] = fmaf(X.x, Wv.x, ar[j]);  ar[j] = fmaf(-X.y, Wv.y, ar[j]);
            ai[j] = fmaf(X.x, Wv.y, ai[j]);  ai[j] = fmaf(X.y, Wv.x, ai[j]);
        }
    }
    #pragma unroll
    for (int j = 0; j < 2; ++j) {
        int u = (half*8 + b0 + 4*j)*64 + o;
        g_O[(size_t)u*800 + mo] = make_float2(ar[j], ai[j]);
    }
}

// ---------------- stage 4+5 fused: inverse H then inverse real W -----------
__global__ __launch_bounds__(256) void invHW(float* __restrict__ out) {
    __shared__ float2 Os[800];
    __shared__ float2 Zst[HH*M2];   // 40KB staging, lives through both phases
    int t = threadIdx.x, img = blockIdx.x;
    const float2* src = &g_O[(size_t)img*800];
    for (int i = t; i < 800; i += 256) Os[i] = src[i];
    __syncthreads();
    // ---- phase 1: inverse DFT along H (parity split), Z -> Zst ----
    {
        int g = t >> 7, h = t & 127;
        int kb = g*10;
        float2 st = g_tw[(2*h) & 255];
        float stc = st.x, sts = st.y;
        float Zer[10], Zei[10], Zor[10], Zoi[10];
        #pragma unroll
        for (int k = 0; k < 10; ++k) { Zer[k]=0.f; Zei[k]=0.f; Zor[k]=0.f; Zoi[k]=0.f; }
        {
            float c = 1.f, s = 0.f;
            #pragma unroll
            for (int rr = 0; rr < 10; ++rr) {
                int r = 2*rr;
                #pragma unroll
                for (int k = 0; k < 10; ++k) {
                    float2 O = Os[r*20 + kb + k];
                    Zer[k] = fmaf(O.x, c, Zer[k]);  Zer[k] = fmaf(-O.y, s, Zer[k]);
                    Zei[k] = fmaf(O.y, c, Zei[k]);  Zei[k] = fmaf(O.x, s, Zei[k]);
                }
                float cn = fmaf(c, stc, -(s*sts)); s = fmaf(s, stc, c*sts); c = cn;
            }
            s = -s;
            #pragma unroll
            for (int rr = 0; rr < 10; ++rr) {
                int r = 20 + 2*rr;
                #pragma unroll
                for (int k = 0; k < 10; ++k) {
                    float2 O = Os[r*20 + kb + k];
                    Zer[k] = fmaf(O.x, c, Zer[k]);  Zer[k] = fmaf(-O.y, s, Zer[k]);
                    Zei[k] = fmaf(O.y, c, Zei[k]);  Zei[k] = fmaf(O.x, s, Zei[k]);
                }
                float cn = fmaf(c, stc, -(s*sts)); s = fmaf(s, stc, c*sts); c = cn;
            }
        }
        {
            float2 t1 = g_tw[t & 127];
            float c = t1.x, s = t1.y;
            #pragma unroll
            for (int rr = 0; rr < 10; ++rr) {
                int r = 1 + 2*rr;
                #pragma unroll
                for (int k = 0; k < 10; ++k) {
                    float2 O = Os[r*20 + kb + k];
                    Zor[k] = fmaf(O.x, c, Zor[k]);  Zor[k] = fmaf(-O.y, s, Zor[k]);
                    Zoi[k] = fmaf(O.y, c, Zoi[k]);  Zoi[k] = fmaf(O.x, s, Zoi[k]);
                }
                if (rr < 9) { float cn = fmaf(c, stc, -(s*sts)); s = fmaf(s, stc, c*sts); c = cn; }
            }
            s = -s;
            #pragma unroll
            for (int rr = 0; rr < 10; ++rr) {
                int r = 21 + 2*rr;
                #pragma unroll
                for (int k = 0; k < 10; ++k) {
                    float2 O = Os[r*20 + kb + k];
                    Zor[k] = fmaf(O.x, c, Zor[k]);  Zor[k] = fmaf(-O.y, s, Zor[k]);
                    Zoi[k] = fmaf(O.y, c, Zoi[k]);  Zoi[k] = fmaf(O.x, s, Zoi[k]);
                }
                float cn = fmaf(c, stc, -(s*sts)); s = fmaf(s, stc, c*sts); c = cn;
            }
        }
        #pragma unroll
        for (int k = 0; k < 10; ++k) {
            Zst[h*20 + kb + k]         = make_float2(Zer[k] + Zor[k], Zei[k] + Zoi[k]);
            Zst[(h + 128)*20 + kb + k] = make_float2(Zer[k] - Zor[k], Zei[k] - Zoi[k]);
        }
    }
    __syncthreads();
    // ---- phase 2: inverse real DFT along W (k-parity fold), 16 passes ----
    int rg = t >> 6, wl = t & 63;
    float2 tww = g_tw[wl];
    float cw = tww.x, sw = tww.y;
    const float SC = 1.f / 65536.f;
    float* obase = out + (size_t)img * 65536;
    for (int p = 0; p < 16; ++p) {
        int rb = p*16 + rg*4;
        float Ae[4]={0,0,0,0}, Ao[4]={0,0,0,0}, Be[4]={0,0,0,0}, Bo[4]={0,0,0,0};
        float c = cw, s = sw;
        #pragma unroll
        for (int k = 1; k < 20; ++k) {
            if (k & 1) {
                #pragma unroll
                for (int j = 0; j < 4; ++j) {
                    float2 Z = Zst[(rb + j)*20 + k];
                    Ao[j] = fmaf(Z.x, c, Ao[j]);
                    Bo[j] = fmaf(Z.y, s, Bo[j]);
                }
            } else {
                #pragma unroll
                for (int j = 0; j < 4; ++j) {
                    float2 Z = Zst[(rb + j)*20 + k];
                    Ae[j] = fmaf(Z.x, c, Ae[j]);
                    Be[j] = fmaf(Z.y, s, Be[j]);
                }
            }
            float cn = fmaf(c, cw, -(s*sw)); s = fmaf(s, cw, c*sw); c = cn;
        }
        #pragma unroll
        for (int j = 0; j < 4; ++j) {
            int row = rb + j;
            float base = Zst[row*20].x;      // Im of DC bin ignored (Hermitian)
            float* orow = obase + row*256;
            float ap = Ae[j] + Ao[j], am = Ae[j] - Ao[j];
            float bp = Be[j] + Bo[j], bm = Be[j] - Bo[j];
            orow[wl]     = (base + 2.f*(ap - bp)) * SC;   // w   (wl=0 -> out[0])
            orow[128-wl] = (base + 2.f*(am + bm)) * SC;   // 128-w (wl=0 -> out[128])
            if (wl) {
                orow[256-wl] = (base + 2.f*(ap + bp)) * SC;
                orow[128+wl] = (base + 2.f*(am - bm)) * SC;
            } else {
                float a64 = 0.f, b64 = 0.f;
                #pragma unroll
                for (int k = 1; k < 20; ++k) {
                    float2 Z = Zst[row*20 + k];
                    int m = k & 3;
                    if (m == 0)      a64 += Z.x;
                    else if (m == 2) a64 -= Z.x;
                    else if (m == 1) b64 += Z.y;
                    else             b64 -= Z.y;
                }
                orow[64]  = (base + 2.f*(a64 - b64)) * SC;
                orow[192] = (base + 2.f*(a64 + b64)) * SC;
            }
        }
    }
}

extern "C" void kernel_launch(void* const* d_in, const int* in_sizes, int n_in,
                              void* d_out, int out_size) {
    const float* x   = (const float*)d_in[0];
    const float* w1r = (const float*)d_in[1];
    const float* w1i = (const float*)d_in[2];
    const float* w2r = (const float*)d_in[3];
    const float* w2i = (const float*)d_in[4];
    float* out = (float*)d_out;

    cudaFuncSetAttribute(fwdWmma, cudaFuncAttributeMaxDynamicSharedMemorySize, SMEM_FWDW);

    initT<<<1, 256>>>();
    wtrans<<<dim3(128, 13), dim3(32, 32)>>>(w1r, w1i, 0);
    wtrans<<<dim3(128, 13), dim3(32, 32)>>>(w2r, w2i, 400);
    fwdWmma<<<NROW/128, 256, SMEM_FWDW>>>(x);   // launch #4 -> profiled
    fwdH<<<NIMG, 256>>>();
    mixk<<<dim3(NRR*M2, 2), 256>>>();
    invHW<<<NIMG, 256>>>(out);
}

// round 14
// speedup vs baseline: 1.3325x; 1.3325x over previous
#include <cuda_runtime.h>

#define BATCH 16
#define CH    64
#define HH    256
#define WW    256
#define M2    20
#define NRR   40
#define NIMG  (BATCH*CH)     /* 1024  */
#define NROW  (NIMG*HH)      /* 262144 */

// ---------------- scratch (device globals; no allocation allowed) ----------
__device__ float2 g_tw[256];          // e^{+2*pi*i*t/256}
__device__ float2 g_Y[NROW*M2];       // forward-W result  [img*256+h][k2]
__device__ float2 g_X[NIMG*NRR*M2];   // forward modes     [img][r][k2]
__device__ float2 g_O[NIMG*NRR*M2];   // mixed modes
__device__ float2 g_W[800*4096];      // transposed weights [mode][i*64+o]

// ---------------- launches 1,2: weight transpose (+ twiddle init) ----------
__global__ __launch_bounds__(1024) void wtrans(const float* __restrict__ wr, const float* __restrict__ wi,
                                               int base) {
    __shared__ float2 tile[32][33];
    int tx = threadIdx.x, ty = threadIdx.y;
    int tid = ty*32 + tx;
    if (blockIdx.x == 0 && blockIdx.y == 0 && tid < 256) {   // idempotent
        double a = 6.283185307179586476925286766559 * (double)tid / 256.0;
        g_tw[tid] = make_float2((float)cos(a), (float)sin(a));
    }
    int u0 = blockIdx.x * 32, o0 = blockIdx.y * 32;
    int off = o0 + tx;
    int u = u0 + ty;
    if (off < 400) tile[ty][tx] = make_float2(wr[u*400 + off], wi[u*400 + off]);
    __syncthreads();
    int offw = o0 + ty;
    if (offw < 400) g_W[(size_t)(base + offw)*4096 + u0 + tx] = tile[tx][ty];
}

// ---------------- stage 1: partial rfft along W (double fold) --------------
// 320 threads: 16 rr-groups x 20 k2; each thread 2 rows (rr, rr+16).
__global__ __launch_bounds__(320) void fwdW(const float* __restrict__ x) {
    __shared__ float2 SAB[2*2080 + 2];   // SA rows stride 65; SB at +2082 (bank shift)
    __shared__ float4 SP[32];            // (x0, x128, s64, d64) per row
    float2* SA = SAB;
    float2* SB = SAB + 2082;
    int t = threadIdx.x;
    const float* xb = x + (size_t)blockIdx.x * 8192;   // 32 rows x 256
    for (int i = t; i < 2048; i += 320) {
        int row = i >> 6, w = i & 63;
        const float* xr = xb + row*256;
        if (w) {
            float a = xr[w], b = xr[256 - w], cc = xr[128 - w], dd = xr[128 + w];
            float s = a + b, d = a - b, s2 = cc + dd, d2 = cc - dd;
            SA[row*65 + w] = make_float2(s + s2, d - d2);   // (sp, dm)
            SB[row*65 + w] = make_float2(s - s2, d + d2);   // (sm, dp)
        } else {
            float x64 = xr[64], x192 = xr[192];
            SP[row] = make_float4(xr[0], xr[128], x64 + x192, x64 - x192);
        }
    }
    __syncthreads();
    int rr = t / 20, k2 = t - 20*(t/20);      // rr 0..15, k2 0..19
    int oddk = k2 & 1;
    const float2* base = oddk ? SB : SA;
    float f4 = (k2 & 2) ? -1.f : 1.f;
    float2 tw = g_tw[k2];
    float c1 = tw.x, s1 = tw.y, c = c1, s = s1;   // start at w=1
    float ar[2] = {0,0}, ai[2] = {0,0};
    for (int w = 1; w < 64; ++w) {
        #pragma unroll
        for (int j = 0; j < 2; ++j) {
            float2 e = base[(rr + 16*j)*65 + w];
            ar[j] = fmaf(e.x, c, ar[j]);
            ai[j] = fmaf(e.y, s, ai[j]);
        }
        float cn = fmaf(c, c1, -(s*s1)); s = fmaf(s, c1, c*s1); c = cn;
    }
    #pragma unroll
    for (int j = 0; j < 2; ++j) {
        int row = rr + 16*j;
        float4 sp = SP[row];
        float re, im;
        if (oddk) { re = ar[j] + sp.x - sp.y;             im = -(ai[j] + f4*sp.w); }
        else      { re = ar[j] + sp.x + sp.y + f4*sp.z;   im = -ai[j]; }
        g_Y[((size_t)blockIdx.x*32 + row)*20 + k2] = make_float2(re, im);
    }
}

// ---------------- stage 2: partial complex DFT along H (radix-4 h-fold) ----
__global__ __launch_bounds__(256) void fwdH() {
    __shared__ float2 Ys[4*1288];   // 4 classes, padded stride 1288 (bank offset 8)
    int t = threadIdx.x, img = blockIdx.x;
    const float2* src = &g_Y[(size_t)img * 5120];
    for (int i = t; i < 5120; i += 256) {
        int m = i / 1280, rsd = i - m*1280;
        Ys[m*1288 + rsd] = src[i];
    }
    __syncthreads();
    for (int i = t; i < 1280; i += 256) {
        float2 a0 = Ys[i], a1 = Ys[1288 + i], a2 = Ys[2576 + i], a3 = Ys[3864 + i];
        float Ax = a0.x - a2.x, Ay = a0.y - a2.y;
        float Bx = a1.x - a3.x, By = a1.y - a3.y;
        float Sx = a0.x + a2.x, Sy = a0.y + a2.y;
        float Tx = a1.x + a3.x, Ty = a1.y + a3.y;
        Ys[i]        = make_float2(Sx + Tx, Sy + Ty);   // q=0
        Ys[1288 + i] = make_float2(Ax + By, Ay - Bx);   // q=1: A - iB
        Ys[2576 + i] = make_float2(Sx - Tx, Sy - Ty);   // q=2
        Ys[3864 + i] = make_float2(Ax - By, Ay + Bx);   // q=3: A + iB
    }
    __syncthreads();
    if (t >= 200) return;
    int r = t / 5, j0 = t - 5*(t/5);          // r 0..39, j0 0..4
    int k1 = r + (r >= 20 ? 216 : 0);
    const float2* base = Ys + (r & 3)*1288 + j0;
    float2 tw = g_tw[k1];
    float c1 = tw.x, s1 = -tw.y;              // step e^{-i th}
    float c = 1.f, s = 0.f;
    float Xr[4] = {0,0,0,0}, Xi[4] = {0,0,0,0};
    for (int h = 0; h < 64; ++h) {
        #pragma unroll
        for (int jj = 0; jj < 4; ++jj) {
            float2 y = base[h*20 + 5*jj];
            Xr[jj] = fmaf(y.x, c, Xr[jj]);  Xr[jj] = fmaf(-y.y, s, Xr[jj]);
            Xi[jj] = fmaf(y.y, c, Xi[jj]);  Xi[jj] = fmaf(y.x, s, Xi[jj]);
        }
        float cn = fmaf(c, c1, -(s*s1)); s = fmaf(s, c1, c*s1); c = cn;
    }
    #pragma unroll
    for (int jj = 0; jj < 4; ++jj)
        g_X[(size_t)img*800 + r*20 + j0 + 5*jj] = make_float2(Xr[jj], Xi[jj]);
}

// ---------------- stage 3: per-mode complex channel mixing (batch-split) ---
__global__ __launch_bounds__(256) void mixk() {
    __shared__ float2 Xs[512];    // [blocal*64+i], blocal 0..7
    __shared__ float2 Ws[4096];   // [i*64+o]
    int t = threadIdx.x, mo = blockIdx.x, half = blockIdx.y;
    for (int u = t; u < 512; u += 256) Xs[u] = g_X[(size_t)(half*512 + u)*800 + mo];
    const float4* wsrc = (const float4*)&g_W[(size_t)mo*4096];
    for (int u = t; u < 2048; u += 256) ((float4*)Ws)[u] = wsrc[u];
    __syncthreads();
    int o = t & 63, b0 = t >> 6;              // b0 0..3
    float ar[2] = {0,0}, ai[2] = {0,0};
    for (int i = 0; i < 64; ++i) {
        float2 Wv = Ws[i*64 + o];
        #pragma unroll
        for (int j = 0; j < 2; ++j) {
            float2 X = Xs[(b0 + 4*j)*64 + i];
            ar[j] = fmaf(X.x, Wv.x, ar[j]);  ar[j] = fmaf(-X.y, Wv.y, ar[j]);
            ai[j] = fmaf(X.x, Wv.y, ai[j]);  ai[j] = fmaf(X.y, Wv.x, ai[j]);
        }
    }
    #pragma unroll
    for (int j = 0; j < 2; ++j) {
        int u = (half*8 + b0 + 4*j)*64 + o;
        g_O[(size_t)u*800 + mo] = make_float2(ar[j], ai[j]);
    }
}

// ---------------- stage 4+5 fused: inverse H then inverse real W -----------
__global__ __launch_bounds__(256) void invHW(float* __restrict__ out) {
    __shared__ float2 Os[800];
    __shared__ float2 Zst[HH*M2];   // 40KB staging, lives through both phases
    int t = threadIdx.x, img = blockIdx.x;
    const float2* src = &g_O[(size_t)img*800];
    for (int i = t; i < 800; i += 256) Os[i] = src[i];
    __syncthreads();
    // ---- phase 1: inverse DFT along H (parity split), Z -> Zst ----
    {
        int g = t >> 7, h = t & 127;
        int kb = g*10;
        float2 st = g_tw[(2*h) & 255];
        float stc = st.x, sts = st.y;
        float Zer[10], Zei[10], Zor[10], Zoi[10];
        #pragma unroll
        for (int k = 0; k < 10; ++k) { Zer[k]=0.f; Zei[k]=0.f; Zor[k]=0.f; Zoi[k]=0.f; }
        {
            float c = 1.f, s = 0.f;
            #pragma unroll
            for (int rr = 0; rr < 10; ++rr) {
                int r = 2*rr;
                #pragma unroll
                for (int k = 0; k < 10; ++k) {
                    float2 O = Os[r*20 + kb + k];
                    Zer[k] = fmaf(O.x, c, Zer[k]);  Zer[k] = fmaf(-O.y, s, Zer[k]);
                    Zei[k] = fmaf(O.y, c, Zei[k]);  Zei[k] = fmaf(O.x, s, Zei[k]);
                }
                float cn = fmaf(c, stc, -(s*sts)); s = fmaf(s, stc, c*sts); c = cn;
            }
            s = -s;
            #pragma unroll
            for (int rr = 0; rr < 10; ++rr) {
                int r = 20 + 2*rr;
                #pragma unroll
                for (int k = 0; k < 10; ++k) {
                    float2 O = Os[r*20 + kb + k];
                    Zer[k] = fmaf(O.x, c, Zer[k]);  Zer[k] = fmaf(-O.y, s, Zer[k]);
                    Zei[k] = fmaf(O.y, c, Zei[k]);  Zei[k] = fmaf(O.x, s, Zei[k]);
                }
                float cn = fmaf(c, stc, -(s*sts)); s = fmaf(s, stc, c*sts); c = cn;
            }
        }
        {
            float2 t1 = g_tw[t & 127];
            float c = t1.x, s = t1.y;
            #pragma unroll
            for (int rr = 0; rr < 10; ++rr) {
                int r = 1 + 2*rr;
                #pragma unroll
                for (int k = 0; k < 10; ++k) {
                    float2 O = Os[r*20 + kb + k];
                    Zor[k] = fmaf(O.x, c, Zor[k]);  Zor[k] = fmaf(-O.y, s, Zor[k]);
                    Zoi[k] = fmaf(O.y, c, Zoi[k]);  Zoi[k] = fmaf(O.x, s, Zoi[k]);
                }
                if (rr < 9) { float cn = fmaf(c, stc, -(s*sts)); s = fmaf(s, stc, c*sts); c = cn; }
            }
            s = -s;
            #pragma unroll
            for (int rr = 0; rr < 10; ++rr) {
                int r = 21 + 2*rr;
                #pragma unroll
                for (int k = 0; k < 10; ++k) {
                    float2 O = Os[r*20 + kb + k];
                    Zor[k] = fmaf(O.x, c, Zor[k]);  Zor[k] = fmaf(-O.y, s, Zor[k]);
                    Zoi[k] = fmaf(O.y, c, Zoi[k]);  Zoi[k] = fmaf(O.x, s, Zoi[k]);
                }
                float cn = fmaf(c, stc, -(s*sts)); s = fmaf(s, stc, c*sts); c = cn;
            }
        }
        #pragma unroll
        for (int k = 0; k < 10; ++k) {
            Zst[h*20 + kb + k]         = make_float2(Zer[k] + Zor[k], Zei[k] + Zoi[k]);
            Zst[(h + 128)*20 + kb + k] = make_float2(Zer[k] - Zor[k], Zei[k] - Zoi[k]);
        }
    }
    __syncthreads();
    // ---- phase 2: inverse real DFT along W; twiddles hoisted to registers ----
    int rg = t >> 6, wl = t & 63;
    float ck[19], sk[19];
    {
        float2 tww = g_tw[wl];
        float cw = tww.x, sw = tww.y, c = cw, s = sw;
        #pragma unroll
        for (int k = 0; k < 19; ++k) {
            ck[k] = c; sk[k] = s;
            float cn = fmaf(c, cw, -(s*sw)); s = fmaf(s, cw, c*sw); c = cn;
        }
    }
    const float SC = 1.f / 65536.f;
    float* obase = out + (size_t)img * 65536;
    for (int p = 0; p < 16; ++p) {
        int rb = p*16 + rg*4;
        float Ae[4]={0,0,0,0}, Ao[4]={0,0,0,0}, Be[4]={0,0,0,0}, Bo[4]={0,0,0,0};
        #pragma unroll
        for (int k = 1; k < 20; ++k) {
            float c = ck[k-1], s = sk[k-1];
            if (k & 1) {
                #pragma unroll
                for (int j = 0; j < 4; ++j) {
                    float2 Z = Zst[(rb + j)*20 + k];
                    Ao[j] = fmaf(Z.x, c, Ao[j]);
                    Bo[j] = fmaf(Z.y, s, Bo[j]);
                }
            } else {
                #pragma unroll
                for (int j = 0; j < 4; ++j) {
                    float2 Z = Zst[(rb + j)*20 + k];
                    Ae[j] = fmaf(Z.x, c, Ae[j]);
                    Be[j] = fmaf(Z.y, s, Be[j]);
                }
            }
        }
        #pragma unroll
        for (int j = 0; j < 4; ++j) {
            int row = rb + j;
            float base = Zst[row*20].x;      // Im of DC bin ignored (Hermitian)
            float* orow = obase + row*256;
            float ap = Ae[j] + Ao[j], am = Ae[j] - Ao[j];
            float bp = Be[j] + Bo[j], bm = Be[j] - Bo[j];
            orow[wl]     = (base + 2.f*(ap - bp)) * SC;   // w   (wl=0 -> out[0])
            orow[128-wl] = (base + 2.f*(am + bm)) * SC;   // 128-w (wl=0 -> out[128])
            if (wl) {
                orow[256-wl] = (base + 2.f*(ap + bp)) * SC;
                orow[128+wl] = (base + 2.f*(am - bm)) * SC;
            } else {
                float a64 = 0.f, b64 = 0.f;
                #pragma unroll
                for (int k = 1; k < 20; ++k) {
                    float2 Z = Zst[row*20 + k];
                    int m = k & 3;
                    if (m == 0)      a64 += Z.x;
                    else if (m == 2) a64 -= Z.x;
                    else if (m == 1) b64 += Z.y;
                    else             b64 -= Z.y;
                }
                orow[64]  = (base + 2.f*(a64 - b64)) * SC;
                orow[192] = (base + 2.f*(a64 + b64)) * SC;
            }
        }
    }
}

extern "C" void kernel_launch(void* const* d_in, const int* in_sizes, int n_in,
                              void* d_out, int out_size) {
    const float* x   = (const float*)d_in[0];
    const float* w1r = (const float*)d_in[1];
    const float* w1i = (const float*)d_in[2];
    const float* w2r = (const float*)d_in[3];
    const float* w2i = (const float*)d_in[4];
    float* out = (float*)d_out;

    wtrans<<<dim3(128, 13), dim3(32, 32)>>>(w1r, w1i, 0);    // + twiddle init
    wtrans<<<dim3(128, 13), dim3(32, 32)>>>(w2r, w2i, 400);
    fwdW<<<NROW/32, 320>>>(x);
    fwdH<<<NIMG, 256>>>();                  // launch #4 -> profiled
    mixk<<<dim3(NRR*M2, 2), 256>>>();
    invHW<<<NIMG, 256>>>(out);
}